// round 6
// baseline (speedup 1.0000x reference)
#include <cuda_runtime.h>
#include <cuda_fp16.h>
#include <cstdint>

#define B_    8
#define HW_   32
#define C_    32
#define F_    64
#define FP_   8      // filters per CTA
#define HO_   30
#define WO_   30
#define K_    288
#define KPADH 296    // halfs per w_sm row; bank(fl)=fl*148 mod 32 distinct per 8-lane phase

__device__ __forceinline__ unsigned h2u(__half2 h)
{
    unsigned u; memcpy(&u, &h, 4); return u;
}
__device__ __forceinline__ __half2 f_as_h2(float f)
{
    __half2 h; unsigned u = __float_as_uint(f); memcpy(&h, &u, 4); return h;
}

#define ACCH(mx, mn, pf, wf)                                                    \
    do {                                                                        \
        __half2 s_;                                                             \
        s_ = __hadd2(f_as_h2(pf.x), f_as_h2(wf.x)); mx = __hmax2(mx, s_); mn = __hmin2(mn, s_); \
        s_ = __hadd2(f_as_h2(pf.y), f_as_h2(wf.y)); mx = __hmax2(mx, s_); mn = __hmin2(mn, s_); \
        s_ = __hadd2(f_as_h2(pf.z), f_as_h2(wf.z)); mx = __hmax2(mx, s_); mn = __hmin2(mn, s_); \
        s_ = __hadd2(f_as_h2(pf.w), f_as_h2(wf.w)); mx = __hmax2(mx, s_); mn = __hmin2(mn, s_); \
    } while (0)

__global__ __launch_bounds__(64, 16)
void tropconv_h2(const float* __restrict__ x,
                 const float* __restrict__ w,
                 const float* __restrict__ bias,
                 float* __restrict__ out)
{
    __shared__ __align__(16) __half w_sm[FP_ * KPADH];   // [8][296]  4736B
    __shared__ __align__(16) __half x_sm[3 * HW_ * C_];  // [3][32][32] 6144B

    const int tid = threadIdx.x;              // 0..63
    const int fq  = blockIdx.x & 7;           // filter octet 0..7
    const int row = blockIdx.x >> 3;          // b*30 + ho
    const int ho  = row % HO_;
    const int b   = row / HO_;

    // ---- inline convert+transpose w slice: global w [k][64] fp32, cols fq*8..fq*8+7 ----
    // idx: f4 = idx&1 selects float4 half of the 8 filters, k = idx>>1
    #pragma unroll 3
    for (int idx = tid; idx < K_ * 2; idx += 64) {
        int k  = idx >> 1;
        int f4 = idx & 1;
        float4 v = *(const float4*)(w + k * F_ + fq * FP_ + f4 * 4);
        __half* dst = w_sm + f4 * 4 * KPADH + k;
        dst[0 * KPADH] = __float2half_rn(v.x);
        dst[1 * KPADH] = __float2half_rn(v.y);
        dst[2 * KPADH] = __float2half_rn(v.z);
        dst[3 * KPADH] = __float2half_rn(v.w);
    }
    // ---- inline convert x slab: 3 rows fp32 -> half (768 float4 -> 768 x 8B) ----
    {
        const float4* src = (const float4*)(x + (b * HW_ + ho) * (HW_ * C_));
        uint2* dst = (uint2*)x_sm;
        #pragma unroll 4
        for (int idx = tid; idx < 3 * HW_ * C_ / 4; idx += 64) {
            float4 v = src[idx];
            dst[idx] = make_uint2(h2u(__floats2half2_rn(v.x, v.y)),
                                  h2u(__floats2half2_rn(v.z, v.w)));
        }
    }
    __syncthreads();

    const int fl   = tid & 7;                 // local filter 0..7
    const int slot = tid >> 3;                // wo-group 0..7
    const int wo_base = slot * 4;

    const char* wrowb = (const char*)w_sm + fl * (KPADH * 2);  // 592B stride, 16B aligned
    const char* xb = (const char*)x_sm;
    const float bv = __ldg(bias + fq * FP_ + fl);

    // clamped column byte-offsets (64B per column)
    int coff[6];
    #pragma unroll
    for (int u = 0; u < 6; ++u) {
        int col = wo_base + u;
        if (col > 31) col = 31;               // garbage only feeds masked stores
        coff[u] = col * 64;
    }

    const __half2 HNEG = __float2half2_rn(-65504.0f);
    const __half2 HPOS = __float2half2_rn(65504.0f);
    __half2 mx2[4], mn2[4];
    #pragma unroll
    for (int t = 0; t < 4; ++t) { mx2[t] = HNEG; mn2[t] = HPOS; }

    #pragma unroll 1
    for (int c4 = 0; c4 < 4; ++c4) {          // 4 chunks of 8 channels
        #pragma unroll
        for (int i = 0; i < 3; ++i) {
            float4 pv[6];                     // broadcast LDS.128 per 8-lane phase
            #pragma unroll
            for (int u = 0; u < 6; ++u)
                pv[u] = *(const float4*)(xb + i * 2048 + coff[u] + c4 * 16);

            #pragma unroll
            for (int j = 0; j < 3; ++j) {
                float4 wv = *(const float4*)(wrowb + (i * 3 + j) * 64 + c4 * 16);
                #pragma unroll
                for (int t = 0; t < 4; ++t)
                    ACCH(mx2[t], mn2[t], pv[j + t], wv);
            }
        }
    }

    #pragma unroll
    for (int t = 0; t < 4; ++t) {
        int wo = wo_base + t;
        if (wo < WO_) {
            float hx = fmaxf(__low2float(mx2[t]), __high2float(mx2[t]));
            float hn = fminf(__low2float(mn2[t]), __high2float(mn2[t]));
            out[(row * WO_ + wo) * F_ + fq * FP_ + fl] = hx - hn + bv;
        }
    }
}

extern "C" void kernel_launch(void* const* d_in, const int* in_sizes, int n_in,
                              void* d_out, int out_size)
{
    const float* x    = (const float*)d_in[0];
    const float* w    = (const float*)d_in[1];
    const float* bias = (const float*)d_in[2];
    float* out        = (float*)d_out;

    tropconv_h2<<<B_ * HO_ * 8, 64>>>(x, w, bias, out);
}

// round 7
// speedup vs baseline: 1.1359x; 1.1359x over previous
#include <cuda_runtime.h>
#include <cuda_fp16.h>
#include <cstdint>

#define B_    8
#define HW_   32
#define C_    32
#define F_    64
#define FQ_   16
#define HO_   30
#define WO_   30
#define K_    288
#define KPADH 296   // halfs per w_sm row: 592B stride -> fl*148 mod 32 distinct per 8-lane phase

// device scratch (allowed: __device__ globals)
__device__ __align__(16) __half g_xh[B_ * HW_ * HW_ * C_];   // 262144 halfs
__device__ __align__(16) __half g_wT[F_ * K_];               // transposed w [f][k]

__device__ __forceinline__ unsigned h2u(__half2 h)
{
    unsigned u; memcpy(&u, &h, 4); return u;
}

// ---- pre-pass: x fp32 -> half (2 float4/thread), w fp32 -> half transposed ----
__global__ void convert_kernel(const float* __restrict__ x, const float* __restrict__ w)
{
    int b = blockIdx.x;
    if (b < 128) {
        int idx = (b * 256 + threadIdx.x) * 2;          // 2 consecutive float4
        #pragma unroll
        for (int r = 0; r < 2; ++r) {
            float4 v = ((const float4*)x)[idx + r];
            ((uint2*)g_xh)[idx + r] = make_uint2(h2u(__floats2half2_rn(v.x, v.y)),
                                                 h2u(__floats2half2_rn(v.z, v.w)));
        }
    } else {
        int j = (b - 128) * 512 + threadIdx.x;
        #pragma unroll
        for (int r = 0; r < 2; ++r, j += 256) {
            if (j < F_ * K_) {
                int f = j / K_, k = j - f * K_;
                g_wT[j] = __float2half_rn(w[k * F_ + f]);
            }
        }
    }
}

__device__ __forceinline__ __half2 f_as_h2(float f)
{
    __half2 h; unsigned u = __float_as_uint(f); memcpy(&h, &u, 4); return h;
}

#define ACCH(mx, mn, pf, wf)                                                    \
    do {                                                                        \
        __half2 s_;                                                             \
        s_ = __hadd2(f_as_h2(pf.x), f_as_h2(wf.x)); mx = __hmax2(mx, s_); mn = __hmin2(mn, s_); \
        s_ = __hadd2(f_as_h2(pf.y), f_as_h2(wf.y)); mx = __hmax2(mx, s_); mn = __hmin2(mn, s_); \
        s_ = __hadd2(f_as_h2(pf.z), f_as_h2(wf.z)); mx = __hmax2(mx, s_); mn = __hmin2(mn, s_); \
        s_ = __hadd2(f_as_h2(pf.w), f_as_h2(wf.w)); mx = __hmax2(mx, s_); mn = __hmin2(mn, s_); \
    } while (0)

__global__ __launch_bounds__(128, 8)
void tropconv_h2(const float* __restrict__ bias, float* __restrict__ out)
{
    __shared__ __align__(16) __half w_sm[FQ_ * KPADH];   // [16][296]  9472B
    __shared__ __align__(16) __half x_sm[3 * HW_ * C_];  // [3][32][32] 6144B

    const int tid = threadIdx.x;
    const int fq  = blockIdx.x & 3;
    const int row = blockIdx.x >> 2;          // b*30 + ho
    const int ho  = row % HO_;
    const int b   = row / HO_;

    // ---- w slice: 576 vec8 (16B) chunks, repacked to padded rows ----
    {
        const char* src = (const char*)(g_wT + fq * FQ_ * K_);
        char* dst = (char*)w_sm;
        #pragma unroll
        for (int idx = tid; idx < 576; idx += 128) {
            int fl = idx / 36;                // 36 chunks per 288-half row
            int k8 = idx - fl * 36;
            *(float4*)(dst + fl * (KPADH * 2) + k8 * 16) =
                *(const float4*)(src + fl * (K_ * 2) + k8 * 16);
        }
    }
    // ---- x slab: 3 rows = 384 vec8 chunks ----
    {
        const float4* src = (const float4*)(g_xh + (b * HW_ + ho) * (HW_ * C_));
        float4* dst = (float4*)x_sm;
        #pragma unroll
        for (int idx = tid; idx < 384; idx += 128)
            dst[idx] = src[idx];
    }
    __syncthreads();

    const int fl   = tid & 15;
    const int slot = tid >> 4;
    const int wo_base = slot * 4;

    const char* wrowb = (const char*)w_sm + fl * (KPADH * 2);   // 592B stride, 16B aligned
    const char* xb = (const char*)x_sm;
    const float bv = __ldg(bias + fq * FQ_ + fl);

    int coff[6];
    #pragma unroll
    for (int u = 0; u < 6; ++u) {
        int col = wo_base + u;
        if (col > 31) col = 31;               // garbage only feeds masked stores
        coff[u] = col * 64;
    }

    const __half2 HNEG = __float2half2_rn(-65504.0f);
    const __half2 HPOS = __float2half2_rn(65504.0f);
    __half2 mx2[4], mn2[4];
    #pragma unroll
    for (int t = 0; t < 4; ++t) { mx2[t] = HNEG; mn2[t] = HPOS; }

    #pragma unroll 1
    for (int c4 = 0; c4 < 4; ++c4) {          // 4 chunks of 8 channels
        #pragma unroll
        for (int i = 0; i < 3; ++i) {
            float4 pv[6];                     // broadcast LDS.128 per 8-lane phase
            #pragma unroll
            for (int u = 0; u < 6; ++u)
                pv[u] = *(const float4*)(xb + i * 2048 + coff[u] + c4 * 16);

            #pragma unroll
            for (int j = 0; j < 3; ++j) {
                float4 wv = *(const float4*)(wrowb + (i * 3 + j) * 64 + c4 * 16);
                #pragma unroll
                for (int t = 0; t < 4; ++t)
                    ACCH(mx2[t], mn2[t], pv[j + t], wv);
            }
        }
    }

    #pragma unroll
    for (int t = 0; t < 4; ++t) {
        int wo = wo_base + t;
        if (wo < WO_) {
            float hx = fmaxf(__low2float(mx2[t]), __high2float(mx2[t]));
            float hn = fminf(__low2float(mn2[t]), __high2float(mn2[t]));
            out[(row * WO_ + wo) * F_ + fq * FQ_ + fl] = hx - hn + bv;
        }
    }
}

extern "C" void kernel_launch(void* const* d_in, const int* in_sizes, int n_in,
                              void* d_out, int out_size)
{
    const float* x    = (const float*)d_in[0];
    const float* w    = (const float*)d_in[1];
    const float* bias = (const float*)d_in[2];
    float* out        = (float*)d_out;

    // 128 blocks x-part (2 float4/thread), 36 blocks w-part
    convert_kernel<<<128 + 36, 256>>>(x, w);
    tropconv_h2<<<B_ * HO_ * 4, 128>>>(bias, out);
}